// round 8
// baseline (speedup 1.0000x reference)
#include <cuda_runtime.h>
#include <cuda_bf16.h>
#include <math.h>

// Problem constants
#define VV   32000
#define EE   500
#define HH   500
#define DD1  800
#define DD2  100
#define CC   2
#define BB   64
#define TT   400
#define G4H  2000            // 4*H
#define MM   (BB*TT)         // 25600 rows of the big GEMMs
#define NREC_BLOCKS 125      // 125 * 4 units = 500
#define GSZ  16384           // floats per group slice (128 quads x 32 b x 4) = 64KB

// ---------------- scratch (device globals; no allocation allowed) ----------------
__device__ float g_xz [(size_t)MM * G4H];     // 204.8 MB, reused for layer1 and layer2
__device__ float g_hs1[(size_t)MM * HH];      // 51.2 MB
__device__ float g_hb0[2 * GSZ];              // [group][slice]
__device__ float g_hb1[2 * GSZ];
__device__ float g_d1 [BB * DD1];
__device__ float g_d2 [BB * DD2];
// tree-barrier state: every counter on its own 128B line
__device__ unsigned g_leaf[2][25][32];
__device__ unsigned g_root[2][32];
__device__ unsigned g_gsns[2][32];
__device__ unsigned g_icnt[32];
__device__ unsigned g_isns[32];

// ---------------- packed f32x2 helpers ----------------
__device__ __forceinline__ unsigned long long dup2(float v){
    unsigned long long r;
    asm("mov.b64 %0, {%1, %1};" : "=l"(r) : "f"(v));
    return r;
}
__device__ __forceinline__ void fma2(unsigned long long &d,
                                     unsigned long long a,
                                     unsigned long long b){
    asm("fma.rn.f32x2 %0, %1, %2, %3;" : "=l"(d) : "l"(a), "l"(b), "l"(d));
}
__device__ __forceinline__ void unpk2(unsigned long long v, float &lo, float &hi){
    asm("mov.b64 {%0, %1}, %2;" : "=f"(lo), "=f"(hi) : "l"(v));
}

// ---------------- cp.async helpers ----------------
__device__ __forceinline__ void cp_async16(unsigned saddr, const void* gptr){
    asm volatile("cp.async.cg.shared.global [%0], [%1], 16;"
                 :: "r"(saddr), "l"(gptr) : "memory");
}
#define CP_COMMIT()  asm volatile("cp.async.commit_group;" ::: "memory")
#define CP_WAIT1()   asm volatile("cp.async.wait_group 1;" ::: "memory")
#define CP_WAIT0()   asm volatile("cp.async.wait_group 0;" ::: "memory")

// =====================================================================
// SGEMM: C[M=25600, N=2000] = A[M,500] @ Bw[500,2000] + bias
// GATHER=1: A row m -> embed[X[b*T+t]] with m = t*64+b
// =====================================================================
template<int GATHER>
__global__ __launch_bounds__(256)
void sgemm_xz(const int* __restrict__ X, const float* __restrict__ A,
              const float* __restrict__ Bw, const float* __restrict__ bias,
              float* __restrict__ Cmat)
{
    __shared__ float As[8][128];
    __shared__ float Bs[8][128];

    const int tid = threadIdx.x;
    const int tx  = tid & 15;
    const int ty  = tid >> 4;
    const int m0  = blockIdx.y * 128;
    const int n0  = blockIdx.x * 128;

    const int ar  = tid >> 1;
    const int akq = (tid & 1) * 4;
    const float* arow_ptr;
    {
        int m = m0 + ar;
        if (GATHER){
            int t = m >> 6, b = m & 63;
            int tok = X[b * TT + t];
            arow_ptr = A + (size_t)tok * EE;
        } else {
            arow_ptr = A + (size_t)m * HH;
        }
    }
    const int bk = tid >> 5;
    const int bn = (tid & 31) * 4;

    unsigned long long acc[8][4];
    #pragma unroll
    for (int i = 0; i < 8; i++)
        #pragma unroll
        for (int j = 0; j < 4; j++) acc[i][j] = 0ULL;

    const float4 f40 = make_float4(0.f, 0.f, 0.f, 0.f);
    float4 aReg, bReg;
    {
        int k  = akq;
        aReg = (k < 500) ? *(const float4*)(arow_ptr + k) : f40;
        int kb = bk, n = n0 + bn;
        bReg = (kb < 500 && n < G4H) ? *(const float4*)(Bw + (size_t)kb * G4H + n) : f40;
    }

    const int KT = 63;
    for (int kt = 0; kt < KT; kt++){
        __syncthreads();
        As[akq+0][ar] = aReg.x; As[akq+1][ar] = aReg.y;
        As[akq+2][ar] = aReg.z; As[akq+3][ar] = aReg.w;
        *(float4*)(&Bs[bk][bn]) = bReg;
        __syncthreads();

        if (kt + 1 < KT){
            int k = (kt+1)*8 + akq;
            aReg = (k < 500) ? *(const float4*)(arow_ptr + k) : f40;
            int kb = (kt+1)*8 + bk, n = n0 + bn;
            bReg = (kb < 500 && n < G4H) ? *(const float4*)(Bw + (size_t)kb * G4H + n) : f40;
        }

        #pragma unroll
        for (int kk = 0; kk < 8; kk++){
            float4 a0 = *(const float4*)(&As[kk][ty*8]);
            float4 a1 = *(const float4*)(&As[kk][ty*8 + 4]);
            const unsigned long long* bp2 = (const unsigned long long*)(&Bs[kk][tx*8]);
            unsigned long long b0 = bp2[0], b1 = bp2[1], b2 = bp2[2], b3 = bp2[3];
            float av[8] = {a0.x,a0.y,a0.z,a0.w,a1.x,a1.y,a1.z,a1.w};
            #pragma unroll
            for (int i = 0; i < 8; i++){
                unsigned long long ad = dup2(av[i]);
                fma2(acc[i][0], ad, b0);
                fma2(acc[i][1], ad, b1);
                fma2(acc[i][2], ad, b2);
                fma2(acc[i][3], ad, b3);
            }
        }
    }

    const int nc = n0 + tx * 8;
    if (nc < G4H){
        float4 bb0 = *(const float4*)(bias + nc);
        float4 bb1 = *(const float4*)(bias + nc + 4);
        #pragma unroll
        for (int i = 0; i < 8; i++){
            int m = m0 + ty*8 + i;
            float o[8];
            unpk2(acc[i][0], o[0], o[1]);
            unpk2(acc[i][1], o[2], o[3]);
            unpk2(acc[i][2], o[4], o[5]);
            unpk2(acc[i][3], o[6], o[7]);
            float4 r0 = make_float4(o[0]+bb0.x, o[1]+bb0.y, o[2]+bb0.z, o[3]+bb0.w);
            float4 r1 = make_float4(o[4]+bb1.x, o[5]+bb1.y, o[6]+bb1.z, o[7]+bb1.w);
            float* cp = Cmat + (size_t)m * G4H + nc;
            *(float4*)(cp)     = r0;
            *(float4*)(cp + 4) = r1;
        }
    }
}

// =====================================================================
// Per-group TREE grid barrier: 25 leaf counters (5 blocks each) -> root(25).
// bar.sync orders the group's weak stores before lt0's release arrive chain:
// leaf acq_rel add -> root acq_rel add -> sense release store; pollers acquire.
// Arrive serialization ~900 cyc vs ~3750 for a single counter.
// =====================================================================
__device__ __forceinline__ void group_barrier(int g, int lt, int leaf, unsigned &sense)
{
    asm volatile("bar.sync %0, 128;" :: "r"(3 + g) : "memory");
    if (lt == 0){
        unsigned target = sense + 1u;
        unsigned old;
        asm volatile("atom.acq_rel.gpu.global.add.u32 %0, [%1], %2;"
                     : "=r"(old) : "l"(&g_leaf[g][leaf][0]), "r"(1u) : "memory");
        bool released = false;
        if (old == 4u){                       // 5th arrival at this leaf
            asm volatile("st.relaxed.gpu.global.u32 [%0], %1;"
                         :: "l"(&g_leaf[g][leaf][0]), "r"(0u) : "memory");
            unsigned r;
            asm volatile("atom.acq_rel.gpu.global.add.u32 %0, [%1], %2;"
                         : "=r"(r) : "l"(&g_root[g][0]), "r"(1u) : "memory");
            if (r == 24u){                    // 25th leaf completion
                asm volatile("st.relaxed.gpu.global.u32 [%0], %1;"
                             :: "l"(&g_root[g][0]), "r"(0u) : "memory");
                asm volatile("st.release.gpu.global.u32 [%0], %1;"
                             :: "l"(&g_gsns[g][0]), "r"(target) : "memory");
                released = true;
            }
        }
        if (!released){
            unsigned v;
            do {
                asm volatile("ld.acquire.gpu.global.u32 %0, [%1];"
                             : "=r"(v) : "l"(&g_gsns[g][0]) : "memory");
            } while ((int)(v - target) < 0);
        }
        sense = target;
    }
    asm volatile("bar.sync %0, 128;" :: "r"(3 + g) : "memory");
}

// =====================================================================
// Persistent LSTM recurrence, two independent batch-groups per SM.
// 125 blocks x 256 threads, 1 block/SM. Group g = threads [g*128,(g+1)*128):
// 32 batches x 4 units. Per-group tree barrier + 64KB h slice.
// h slice layout (quad-packed): h[g][q*128 + bl*4 + (k&3)], q=k>>2, q<128.
// Staging: cp.async in 2x32KB chunks; compute quads 0..63 overlaps chunk 1.
// xz for step t+1 prefetched into registers during step t's compute.
// =====================================================================
__global__ void lstm_rec(const float* __restrict__ xz, const float* __restrict__ Wh,
                         float* __restrict__ hs_out, int store_hs,
                         float* __restrict__ hb0, float* __restrict__ hb1)
{
    extern __shared__ float smem[];
    float* hsm = smem;                 // 2 * 16384 floats (128 KB)
    float* wsm = smem + 2 * GSZ;       // 8000 floats (32 KB)

    const int tid  = threadIdx.x;
    const int g    = tid >> 7;         // batch group 0/1
    const int lt   = tid & 127;        // lane within group
    const int bl   = lt & 31;          // batch within group
    const int u    = (lt >> 5) & 3;    // unit within block slice
    const int u0   = blockIdx.x * 4;
    const int uu   = u0 + u;
    const int b    = g * 32 + bl;      // global batch
    const int leaf = blockIdx.x / 5;   // 0..24

    unsigned gsense = 0, isense = 0;
    if (lt == 0)
        asm volatile("ld.relaxed.gpu.global.u32 %0, [%1];" : "=r"(gsense) : "l"(&g_gsns[g][0]) : "memory");
    if (tid == 0)
        asm volatile("ld.relaxed.gpu.global.u32 %0, [%1];" : "=r"(isense) : "l"(&g_isns[0]) : "memory");

    // cache weight slice: wsm[k*16 + uw*4 + gate] = Wh[k*2000 + gate*500 + u0+uw]
    for (int idx = tid; idx < 500 * 16; idx += 256){
        int k = idx >> 4, r = idx & 15;
        int uw = r >> 2, gg = r & 3;
        wsm[idx] = Wh[(size_t)k * G4H + gg * HH + u0 + uw];
    }
    // zero both h buffers (incl. pad quads)
    {
        int gt = blockIdx.x * 256 + tid;
        float4 z4 = make_float4(0.f, 0.f, 0.f, 0.f);
        for (int i = gt; i < (2 * GSZ) / 4; i += NREC_BLOCKS * 256){
            ((float4*)hb0)[i] = z4;
            ((float4*)hb1)[i] = z4;
        }
    }
    // init: full-grid single-counter barrier (one-time cost)
    __syncthreads();
    if (tid == 0){
        unsigned target = isense + 1u, old;
        asm volatile("atom.acq_rel.gpu.global.add.u32 %0, [%1], %2;"
                     : "=r"(old) : "l"(&g_icnt[0]), "r"(1u) : "memory");
        if (old == (unsigned)(NREC_BLOCKS - 1)){
            asm volatile("st.relaxed.gpu.global.u32 [%0], %1;" :: "l"(&g_icnt[0]), "r"(0u) : "memory");
            asm volatile("st.release.gpu.global.u32 [%0], %1;" :: "l"(&g_isns[0]), "r"(target) : "memory");
        } else {
            unsigned v;
            do {
                asm volatile("ld.acquire.gpu.global.u32 %0, [%1];" : "=r"(v) : "l"(&g_isns[0]) : "memory");
            } while ((int)(v - target) < 0);
        }
    }
    __syncthreads();

    float* hsg = hsm + g * GSZ;
    const unsigned hsg_s = (unsigned)__cvta_generic_to_shared(hsg);
    float cst = 0.f;
    const int hoff = g * GSZ + (uu >> 2) * 128 + bl * 4 + (uu & 3);
    const float* xzb = xz + (size_t)b * G4H + uu;

    // prefetch xz for t = 0
    float xi = __ldcs(xzb);
    float xj = __ldcs(xzb + 500);
    float xf = __ldcs(xzb + 1000);
    float xo = __ldcs(xzb + 1500);

    for (int t = 0; t < TT; t++){
        const float* hprev = ((t & 1) ? hb1 : hb0) + g * GSZ;
        float*       hnext = ((t & 1) ? hb0 : hb1);

        // stage this group's 64KB slice in two 32KB chunks (L1-bypass, async)
        #pragma unroll
        for (int i = 0; i < 16; i++){
            int idx = lt + i * 128;
            cp_async16(hsg_s + idx * 16, (const float4*)hprev + idx);
        }
        CP_COMMIT();
        #pragma unroll
        for (int i = 16; i < 32; i++){
            int idx = lt + i * 128;
            cp_async16(hsg_s + idx * 16, (const float4*)hprev + idx);
        }
        CP_COMMIT();

        // prefetch next step's xz (lands during compute below)
        float nxi = 0.f, nxj = 0.f, nxf = 0.f, nxo = 0.f;
        if (t + 1 < TT){
            size_t mr = (size_t)(t + 1) * BB * G4H;
            nxi = __ldcs(xzb + mr);
            nxj = __ldcs(xzb + mr + 500);
            nxf = __ldcs(xzb + mr + 1000);
            nxo = __ldcs(xzb + mr + 1500);
        }

        unsigned long long aij = 0ULL, afo = 0ULL;

        CP_WAIT1();            // chunk 0 (quads 0..63) resident
        asm volatile("bar.sync %0, 128;" :: "r"(3 + g) : "memory");

        #pragma unroll 4
        for (int q = 0; q < 64; q++){
            float4 h4 = *(const float4*)(hsg + q * 128 + bl * 4);
            const float* wq = wsm + q * 64 + u * 4;
            ulonglong2 w0 = *(const ulonglong2*)(wq);
            ulonglong2 w1 = *(const ulonglong2*)(wq + 16);
            ulonglong2 w2 = *(const ulonglong2*)(wq + 32);
            ulonglong2 w3 = *(const ulonglong2*)(wq + 48);
            fma2(aij, dup2(h4.x), w0.x); fma2(afo, dup2(h4.x), w0.y);
            fma2(aij, dup2(h4.y), w1.x); fma2(afo, dup2(h4.y), w1.y);
            fma2(aij, dup2(h4.z), w2.x); fma2(afo, dup2(h4.z), w2.y);
            fma2(aij, dup2(h4.w), w3.x); fma2(afo, dup2(h4.w), w3.y);
        }

        CP_WAIT0();            // chunk 1 (quads 64..127) resident
        asm volatile("bar.sync %0, 128;" :: "r"(3 + g) : "memory");

        #pragma unroll 4
        for (int q = 64; q < 125; q++){
            float4 h4 = *(const float4*)(hsg + q * 128 + bl * 4);
            const float* wq = wsm + q * 64 + u * 4;
            ulonglong2 w0 = *(const ulonglong2*)(wq);
            ulonglong2 w1 = *(const ulonglong2*)(wq + 16);
            ulonglong2 w2 = *(const ulonglong2*)(wq + 32);
            ulonglong2 w3 = *(const ulonglong2*)(wq + 48);
            fma2(aij, dup2(h4.x), w0.x); fma2(afo, dup2(h4.x), w0.y);
            fma2(aij, dup2(h4.y), w1.x); fma2(afo, dup2(h4.y), w1.y);
            fma2(aij, dup2(h4.z), w2.x); fma2(afo, dup2(h4.z), w2.y);
            fma2(aij, dup2(h4.w), w3.x); fma2(afo, dup2(h4.w), w3.y);
        }

        float si, sj, sf, so;
        unpk2(aij, si, sj);
        unpk2(afo, sf, so);
        float zi = si + xi, zj = sj + xj, zf = sf + xf, zo = so + xo;

        float ig = 1.f / (1.f + expf(-zi));
        float fg = 1.f / (1.f + expf(-(zf + 1.f)));
        float og = 1.f / (1.f + expf(-zo));
        float jt = tanhf(zj);
        cst = fg * cst + ig * jt;
        float hv = og * tanhf(cst);

        xi = nxi; xj = nxj; xf = nxf; xo = nxo;

        __stcg(hnext + hoff, hv);
        if (store_hs)
            hs_out[(size_t)(t * BB + b) * HH + uu] = hv;

        group_barrier(g, lt, leaf, gsense);
    }
}

// =====================================================================
// Small dense layers. transposed_in: in uses the grouped quad-packed h layout.
// =====================================================================
__global__ void dense_kernel(const float* __restrict__ in, const float* __restrict__ W,
                             const float* __restrict__ bias, float* __restrict__ out,
                             int Kdim, int Ndim, int transposed_in, int do_relu)
{
    int gidx = blockIdx.x * blockDim.x + threadIdx.x;
    if (gidx >= BB * Ndim) return;
    int bv = gidx / Ndim;
    int j  = gidx - bv * Ndim;
    float acc = bias[j];
    if (transposed_in){
        int base = (bv >> 5) * GSZ + (bv & 31) * 4;
        for (int k = 0; k < Kdim; k++)
            acc += in[base + (k >> 2) * 128 + (k & 3)] * W[k * Ndim + j];
    } else {
        for (int k = 0; k < Kdim; k++)
            acc += in[bv * Kdim + k] * W[k * Ndim + j];
    }
    out[gidx] = do_relu ? fmaxf(acc, 0.f) : acc;
}

// =====================================================================
// Launch
// =====================================================================
#define REC_SMEM ((2*GSZ + 500*16) * (int)sizeof(float))   // 163072 B

extern "C" void kernel_launch(void* const* d_in, const int* in_sizes, int n_in,
                              void* d_out, int out_size)
{
    const int*   X     = (const int*)  d_in[0];
    const float* embed = (const float*)d_in[1];
    const float* k1    = (const float*)d_in[2];
    const float* b1    = (const float*)d_in[3];
    const float* k2    = (const float*)d_in[4];
    const float* b2    = (const float*)d_in[5];
    const float* w1    = (const float*)d_in[6];
    const float* bw1   = (const float*)d_in[7];
    const float* w2    = (const float*)d_in[8];
    const float* bw2   = (const float*)d_in[9];
    const float* wp    = (const float*)d_in[10];
    const float* bp    = (const float*)d_in[11];
    float* out = (float*)d_out;

    float *xz, *hs1, *hb0, *hb1, *d1, *d2;
    cudaGetSymbolAddress((void**)&xz,  g_xz);
    cudaGetSymbolAddress((void**)&hs1, g_hs1);
    cudaGetSymbolAddress((void**)&hb0, g_hb0);
    cudaGetSymbolAddress((void**)&hb1, g_hb1);
    cudaGetSymbolAddress((void**)&d1,  g_d1);
    cudaGetSymbolAddress((void**)&d2,  g_d2);

    cudaFuncSetAttribute(lstm_rec, cudaFuncAttributeMaxDynamicSharedMemorySize, REC_SMEM);

    dim3 ggrid(16, 200);   // N tiles x M tiles

    // layer 1: xz1 = embed[X] @ k1[:E] + b1 ; then recurrence (stores hs1)
    sgemm_xz<1><<<ggrid, 256>>>(X, embed, k1, b1, xz);
    lstm_rec<<<NREC_BLOCKS, 256, REC_SMEM>>>(xz, k1 + (size_t)EE * G4H,
                                             hs1, 1, hb0, hb1);

    // layer 2: xz2 = hs1 @ k2[:H] + b2 ; recurrence (final h only)
    sgemm_xz<0><<<ggrid, 256>>>(nullptr, hs1, k2, b2, xz);
    lstm_rec<<<NREC_BLOCKS, 256, REC_SMEM>>>(xz, k2 + (size_t)HH * G4H,
                                             nullptr, 0, hb0, hb1);

    // head: T=400 even -> final h in hb0 (written at t=399)
    dense_kernel<<<(BB*DD1 + 255)/256, 256>>>(hb0, w1, bw1, d1, HH,  DD1, 1, 1);
    dense_kernel<<<(BB*DD2 + 255)/256, 256>>>(d1,  w2, bw2, d2, DD1, DD2, 0, 1);
    dense_kernel<<<1, BB*CC>>>(d2, wp, bp, out, DD2, CC, 0, 0);
}